// round 14
// baseline (speedup 1.0000x reference)
#include <cuda_runtime.h>
#include <cuda_fp16.h>
#include <cstdint>

// Problem constants (fixed shapes)
#define T_TOK  16384
#define DMODEL 512
#define FFDIM  2048
#define NEXP   8

// ---------------- device scratch (alloc-free rule: __device__ globals) --------
__device__ __align__(128) __half g_xs [(size_t)T_TOK * DMODEL];          // scaled tokens fp16
__device__ __align__(128) __half g_H  [(size_t)T_TOK * FFDIM];           // hidden acts fp16 (sorted order)
__device__ __align__(128) __half g_W1h[(size_t)NEXP * DMODEL * FFDIM];   // fp16 weights
__device__ __align__(128) __half g_W2h[(size_t)NEXP * FFDIM * DMODEL];
__device__ int g_routes[T_TOK];
__device__ int g_perm  [T_TOK];
__device__ int g_base  [NEXP];
__device__ int g_count [NEXP];

// ---------------- small PTX helpers ------------------------------------------
__device__ __forceinline__ uint32_t smem_u32(const void* p) {
    return (uint32_t)__cvta_generic_to_shared(p);
}
__device__ __forceinline__ void ldm_x4(uint32_t r[4], uint32_t addr) {
    asm volatile("ldmatrix.sync.aligned.m8n8.x4.shared.b16 {%0,%1,%2,%3}, [%4];\n"
                 : "=r"(r[0]), "=r"(r[1]), "=r"(r[2]), "=r"(r[3]) : "r"(addr));
}
__device__ __forceinline__ void ldm_x4_t(uint32_t r[4], uint32_t addr) {
    asm volatile("ldmatrix.sync.aligned.m8n8.x4.trans.shared.b16 {%0,%1,%2,%3}, [%4];\n"
                 : "=r"(r[0]), "=r"(r[1]), "=r"(r[2]), "=r"(r[3]) : "r"(addr));
}
__device__ __forceinline__ void mma_16816(float c[4], const uint32_t a[4],
                                          uint32_t b0, uint32_t b1) {
    asm volatile("mma.sync.aligned.m16n8k16.row.col.f32.f16.f16.f32 "
                 "{%0,%1,%2,%3}, {%4,%5,%6,%7}, {%8,%9}, {%0,%1,%2,%3};\n"
                 : "+f"(c[0]), "+f"(c[1]), "+f"(c[2]), "+f"(c[3])
                 : "r"(a[0]), "r"(a[1]), "r"(a[2]), "r"(a[3]), "r"(b0), "r"(b1));
}

// ---------------- kernel 1: weight fp32 -> fp16 ------------------------------
__global__ __launch_bounds__(256) void convw_kernel(const float* __restrict__ W1,
                                                    const float* __restrict__ W2) {
    size_t i = (size_t)blockIdx.x * 256 + threadIdx.x;   // over 4,194,304 float2 pairs
    float2 a = *reinterpret_cast<const float2*>(W1 + 2 * i);
    *reinterpret_cast<__half2*>(g_W1h + 2 * i) = __floats2half2_rn(a.x, a.y);
    float2 b = *reinterpret_cast<const float2*>(W2 + 2 * i);
    *reinterpret_cast<__half2*>(g_W2h + 2 * i) = __floats2half2_rn(b.x, b.y);
}

// ---------------- kernel 2: routing (warp per token) --------------------------
__global__ __launch_bounds__(256) void route_kernel(const float* __restrict__ x,
                                                    const float* __restrict__ Wg,
                                                    const float* __restrict__ bg) {
    __shared__ float sWg[DMODEL * NEXP];                 // 16KB
    for (int i = threadIdx.x; i < DMODEL * NEXP; i += 256) sWg[i] = Wg[i];
    __syncthreads();

    int warp = threadIdx.x >> 5, lane = threadIdx.x & 31;
    int t = blockIdx.x * 8 + warp;
    const float* xp = x + (size_t)t * DMODEL;

    float4 fv[4];
    float acc[NEXP];
    #pragma unroll
    for (int e = 0; e < NEXP; e++) acc[e] = 0.f;

    #pragma unroll
    for (int i = 0; i < 4; i++) {
        int d0 = (lane + 32 * i) * 4;
        fv[i] = *reinterpret_cast<const float4*>(xp + d0);
        const float* w = &sWg[d0 * NEXP];
        #pragma unroll
        for (int e = 0; e < NEXP; e++)
            acc[e] += fv[i].x * w[e] + fv[i].y * w[NEXP + e]
                    + fv[i].z * w[2 * NEXP + e] + fv[i].w * w[3 * NEXP + e];
    }
    #pragma unroll
    for (int off = 16; off; off >>= 1)
        #pragma unroll
        for (int e = 0; e < NEXP; e++) acc[e] += __shfl_xor_sync(0xffffffffu, acc[e], off);

    #pragma unroll
    for (int e = 0; e < NEXP; e++) acc[e] += __ldg(&bg[e]);

    float lmax = acc[0]; int arg = 0;
    #pragma unroll
    for (int e = 1; e < NEXP; e++) if (acc[e] > lmax) { lmax = acc[e]; arg = e; }  // first-max tie-break
    float sum = 0.f;
    #pragma unroll
    for (int e = 0; e < NEXP; e++) sum += __expf(acc[e] - lmax);
    float pmax = 1.f / sum;                              // softmax max prob

    if (lane == 0) g_routes[t] = arg;

    __half* outp = g_xs + (size_t)t * DMODEL;
    #pragma unroll
    for (int i = 0; i < 4; i++) {
        int d0 = (lane + 32 * i) * 4;
        *reinterpret_cast<__half2*>(outp + d0)     = __floats2half2_rn(fv[i].x * pmax, fv[i].y * pmax);
        *reinterpret_cast<__half2*>(outp + d0 + 2) = __floats2half2_rn(fv[i].z * pmax, fv[i].w * pmax);
    }
}

// ---------------- kernel 3: stable counting sort (1 CTA) ----------------------
__global__ __launch_bounds__(256) void scan_kernel() {
    __shared__ int cnt[256][NEXP];                       // 8KB
    __shared__ int sbase[NEXP];
    int tid = threadIdx.x;
    int c[NEXP];
    #pragma unroll
    for (int e = 0; e < NEXP; e++) c[e] = 0;
    int start = tid * 64;                                // 256*64 = 16384
    #pragma unroll 8
    for (int i = 0; i < 64; i++) c[g_routes[start + i]]++;
    #pragma unroll
    for (int e = 0; e < NEXP; e++) cnt[tid][e] = c[e];
    __syncthreads();
    if (tid == 0) {
        int tot[NEXP];
        for (int e = 0; e < NEXP; e++) {
            int run = 0;
            for (int t = 0; t < 256; t++) { int v = cnt[t][e]; cnt[t][e] = run; run += v; }
            tot[e] = run;
        }
        int accb = 0;
        for (int e = 0; e < NEXP; e++) {
            sbase[e] = accb; g_base[e] = accb; g_count[e] = tot[e]; accb += tot[e];
        }
    }
    __syncthreads();
    int off[NEXP];
    #pragma unroll
    for (int e = 0; e < NEXP; e++) off[e] = sbase[e] + cnt[tid][e];
    for (int i = 0; i < 64; i++) {
        int t = start + i;
        int e = g_routes[t];
        g_perm[off[e]++] = t;                            // stable: chunk-order within thread
    }
}

// ---------------- kernel 4/5: grouped GEMM (fp16 HMMA, fp32 accum) -----------
// FIRST=true : H = relu(Xs[perm] @ W1[e] + b1[e])  -> g_H (fp16, sorted rows)
// FIRST=false: out = H @ W2[e] + b2[e]             -> outF (fp32, sorted rows)
template<int K, int N, bool FIRST>
__global__ __launch_bounds__(256) void ffn_gemm(const float* __restrict__ biasAll,
                                                float* __restrict__ outF) {
    constexpr int BM = 128, BN = 128, BK = 32;
    int e = blockIdx.z;
    int cntE = g_count[e];
    int mt = blockIdx.y * BM;
    if (mt >= cntE) return;                              // empty tile -> cheap exit
    int m0 = g_base[e] + mt;
    int rows = cntE - mt; if (rows > BM) rows = BM;
    int n0 = blockIdx.x * BN;

    const __half* A  = FIRST ? g_xs : g_H;
    const __half* Bp = (FIRST ? g_W1h : g_W2h) + (size_t)e * K * N + n0;
    const float* bias = biasAll + (size_t)e * N;

    __shared__ __half As[BM][BK + 8];                    // 80B row stride (16B-mult)
    __shared__ __half Bs[BK][BN + 8];                    // 272B row stride
    __shared__ int sperm[BM];

    int tid = threadIdx.x, lane = tid & 31, warp = tid >> 5;
    int wm = warp & 1, wn = warp >> 1;                   // 2x4 warp grid, warp tile 64x32

    if constexpr (FIRST) {
        if (tid < BM) sperm[tid] = (tid < rows) ? g_perm[m0 + tid] : 0;
        __syncthreads();
    }

    float acc[4][4][4];
    #pragma unroll
    for (int a = 0; a < 4; a++)
        #pragma unroll
        for (int b = 0; b < 4; b++)
            #pragma unroll
            for (int cdx = 0; cdx < 4; cdx++) acc[a][b][cdx] = 0.f;

    #pragma unroll 1
    for (int k0 = 0; k0 < K; k0 += BK) {
        // A tile: 128x32 halves = 512 uint4, 2 per thread
        #pragma unroll
        for (int p = 0; p < 2; p++) {
            int v = tid + p * 256;
            int r = v >> 2, kc = (v & 3) << 3;
            uint4 val = make_uint4(0u, 0u, 0u, 0u);
            if (r < rows) {
                size_t arow = FIRST ? (size_t)sperm[r] : (size_t)(m0 + r);
                val = *reinterpret_cast<const uint4*>(A + arow * K + k0 + kc);
            }
            *reinterpret_cast<uint4*>(&As[r][kc]) = val;
        }
        // B tile: 32x128 halves = 512 uint4
        #pragma unroll
        for (int p = 0; p < 2; p++) {
            int v = tid + p * 256;
            int r = v >> 4, ncol = (v & 15) << 3;
            *reinterpret_cast<uint4*>(&Bs[r][ncol]) =
                *reinterpret_cast<const uint4*>(Bp + (size_t)(k0 + r) * N + ncol);
        }
        __syncthreads();

        #pragma unroll
        for (int ks = 0; ks < 2; ks++) {
            int kk = ks * 16;
            uint32_t af[4][4];
            #pragma unroll
            for (int mi = 0; mi < 4; mi++) {
                uint32_t ad = smem_u32(&As[wm * 64 + mi * 16 + (lane & 15)][kk + ((lane >> 4) << 3)]);
                ldm_x4(af[mi], ad);
            }
            #pragma unroll
            for (int nh = 0; nh < 2; nh++) {
                uint32_t bf[4];
                uint32_t bd = smem_u32(&Bs[kk + (lane & 15)][wn * 32 + nh * 16 + ((lane >> 4) << 3)]);
                ldm_x4_t(bf, bd);
                #pragma unroll
                for (int mi = 0; mi < 4; mi++) {
                    mma_16816(acc[mi][nh * 2 + 0], af[mi], bf[0], bf[1]);
                    mma_16816(acc[mi][nh * 2 + 1], af[mi], bf[2], bf[3]);
                }
            }
        }
        __syncthreads();
    }

    // epilogue: +bias, (relu->fp16) or fp32 store; rows are output-order contiguous
    #pragma unroll
    for (int mi = 0; mi < 4; mi++) {
        #pragma unroll
        for (int ni = 0; ni < 4; ni++) {
            int col = wn * 32 + ni * 8 + (lane & 3) * 2;
            int gn = n0 + col;
            float bv0 = __ldg(&bias[gn]);
            float bv1 = __ldg(&bias[gn + 1]);
            #pragma unroll
            for (int h = 0; h < 2; h++) {
                int row = wm * 64 + mi * 16 + (lane >> 2) + h * 8;
                if (row < rows) {
                    float v0 = acc[mi][ni][2 * h + 0] + bv0;
                    float v1 = acc[mi][ni][2 * h + 1] + bv1;
                    size_t goff = (size_t)(m0 + row) * N + gn;
                    if constexpr (FIRST) {
                        v0 = fmaxf(v0, 0.f); v1 = fmaxf(v1, 0.f);
                        *reinterpret_cast<__half2*>(g_H + goff) = __floats2half2_rn(v0, v1);
                    } else {
                        *reinterpret_cast<float2*>(outF + goff) = make_float2(v0, v1);
                    }
                }
            }
        }
    }
}

// ---------------- launcher ----------------------------------------------------
extern "C" void kernel_launch(void* const* d_in, const int* in_sizes, int n_in,
                              void* d_out, int out_size) {
    const float* x  = (const float*)d_in[0];   // [8,2048,512]
    const float* Wg = (const float*)d_in[1];   // [512,8]
    const float* bg = (const float*)d_in[2];   // [8]
    const float* W1 = (const float*)d_in[3];   // [8,512,2048]
    const float* b1 = (const float*)d_in[4];   // [8,2048]
    const float* W2 = (const float*)d_in[5];   // [8,2048,512]
    const float* b2 = (const float*)d_in[6];   // [8,512]
    float* out = (float*)d_out;                // [8,2048,512]

    convw_kernel<<<16384, 256>>>(W1, W2);
    route_kernel<<<T_TOK / 8, 256>>>(x, Wg, bg);
    scan_kernel<<<1, 256>>>();
    {
        dim3 g(FFDIM / 128, T_TOK / 128, NEXP);
        ffn_gemm<DMODEL, FFDIM, true><<<g, 256>>>(b1, nullptr);
    }
    {
        dim3 g(DMODEL / 128, T_TOK / 128, NEXP);
        ffn_gemm<FFDIM, DMODEL, false><<<g, 256>>>(b2, out);
    }
}

// round 15
// speedup vs baseline: 1.0032x; 1.0032x over previous
#include <cuda_runtime.h>
#include <cuda_fp16.h>
#include <cstdint>

// Problem constants (fixed shapes)
#define T_TOK  16384
#define DMODEL 512
#define FFDIM  2048
#define NEXP   8

// ---------------- device scratch (alloc-free rule: __device__ globals) --------
__device__ __align__(128) __half g_xs [(size_t)T_TOK * DMODEL];          // scaled tokens fp16
__device__ __align__(128) __half g_H  [(size_t)T_TOK * FFDIM];           // hidden acts fp16 (sorted order)
__device__ __align__(128) __half g_W1h[(size_t)NEXP * DMODEL * FFDIM];   // fp16 weights
__device__ __align__(128) __half g_W2h[(size_t)NEXP * FFDIM * DMODEL];
__device__ int g_routes[T_TOK];
__device__ int g_perm  [T_TOK];
__device__ int g_base  [NEXP];
__device__ int g_count [NEXP];

// ---------------- small PTX helpers ------------------------------------------
__device__ __forceinline__ uint32_t smem_u32(const void* p) {
    return (uint32_t)__cvta_generic_to_shared(p);
}
__device__ __forceinline__ void ldm_x4(uint32_t r[4], uint32_t addr) {
    asm volatile("ldmatrix.sync.aligned.m8n8.x4.shared.b16 {%0,%1,%2,%3}, [%4];\n"
                 : "=r"(r[0]), "=r"(r[1]), "=r"(r[2]), "=r"(r[3]) : "r"(addr));
}
__device__ __forceinline__ void ldm_x4_t(uint32_t r[4], uint32_t addr) {
    asm volatile("ldmatrix.sync.aligned.m8n8.x4.trans.shared.b16 {%0,%1,%2,%3}, [%4];\n"
                 : "=r"(r[0]), "=r"(r[1]), "=r"(r[2]), "=r"(r[3]) : "r"(addr));
}
__device__ __forceinline__ void mma_16816(float c[4], const uint32_t a[4],
                                          uint32_t b0, uint32_t b1) {
    asm volatile("mma.sync.aligned.m16n8k16.row.col.f32.f16.f16.f32 "
                 "{%0,%1,%2,%3}, {%4,%5,%6,%7}, {%8,%9}, {%0,%1,%2,%3};\n"
                 : "+f"(c[0]), "+f"(c[1]), "+f"(c[2]), "+f"(c[3])
                 : "r"(a[0]), "r"(a[1]), "r"(a[2]), "r"(a[3]), "r"(b0), "r"(b1));
}

// ---------------- kernel 1: weight fp32 -> fp16 ------------------------------
__global__ __launch_bounds__(256) void convw_kernel(const float* __restrict__ W1,
                                                    const float* __restrict__ W2) {
    size_t i = (size_t)blockIdx.x * 256 + threadIdx.x;   // over 4,194,304 float2 pairs
    float2 a = *reinterpret_cast<const float2*>(W1 + 2 * i);
    *reinterpret_cast<__half2*>(g_W1h + 2 * i) = __floats2half2_rn(a.x, a.y);
    float2 b = *reinterpret_cast<const float2*>(W2 + 2 * i);
    *reinterpret_cast<__half2*>(g_W2h + 2 * i) = __floats2half2_rn(b.x, b.y);
}

// ---------------- kernel 2: routing (warp per token) --------------------------
__global__ __launch_bounds__(256) void route_kernel(const float* __restrict__ x,
                                                    const float* __restrict__ Wg,
                                                    const float* __restrict__ bg) {
    __shared__ float sWg[DMODEL * NEXP];                 // 16KB
    for (int i = threadIdx.x; i < DMODEL * NEXP; i += 256) sWg[i] = Wg[i];
    __syncthreads();

    int warp = threadIdx.x >> 5, lane = threadIdx.x & 31;
    int t = blockIdx.x * 8 + warp;
    const float* xp = x + (size_t)t * DMODEL;

    float4 fv[4];
    float acc[NEXP];
    #pragma unroll
    for (int e = 0; e < NEXP; e++) acc[e] = 0.f;

    #pragma unroll
    for (int i = 0; i < 4; i++) {
        int d0 = (lane + 32 * i) * 4;
        fv[i] = *reinterpret_cast<const float4*>(xp + d0);
        const float* w = &sWg[d0 * NEXP];
        #pragma unroll
        for (int e = 0; e < NEXP; e++)
            acc[e] += fv[i].x * w[e] + fv[i].y * w[NEXP + e]
                    + fv[i].z * w[2 * NEXP + e] + fv[i].w * w[3 * NEXP + e];
    }
    #pragma unroll
    for (int off = 16; off; off >>= 1)
        #pragma unroll
        for (int e = 0; e < NEXP; e++) acc[e] += __shfl_xor_sync(0xffffffffu, acc[e], off);

    #pragma unroll
    for (int e = 0; e < NEXP; e++) acc[e] += __ldg(&bg[e]);

    float lmax = acc[0]; int arg = 0;
    #pragma unroll
    for (int e = 1; e < NEXP; e++) if (acc[e] > lmax) { lmax = acc[e]; arg = e; }  // first-max tie-break
    float sum = 0.f;
    #pragma unroll
    for (int e = 0; e < NEXP; e++) sum += __expf(acc[e] - lmax);
    float pmax = 1.f / sum;                              // softmax max prob

    if (lane == 0) g_routes[t] = arg;

    __half* outp = g_xs + (size_t)t * DMODEL;
    #pragma unroll
    for (int i = 0; i < 4; i++) {
        int d0 = (lane + 32 * i) * 4;
        *reinterpret_cast<__half2*>(outp + d0)     = __floats2half2_rn(fv[i].x * pmax, fv[i].y * pmax);
        *reinterpret_cast<__half2*>(outp + d0 + 2) = __floats2half2_rn(fv[i].z * pmax, fv[i].w * pmax);
    }
}

// ---------------- kernel 3: stable counting sort (1 CTA) ----------------------
__global__ __launch_bounds__(256) void scan_kernel() {
    __shared__ int cnt[256][NEXP];                       // 8KB
    __shared__ int sbase[NEXP];
    int tid = threadIdx.x;
    int c[NEXP];
    #pragma unroll
    for (int e = 0; e < NEXP; e++) c[e] = 0;
    int start = tid * 64;                                // 256*64 = 16384
    #pragma unroll 8
    for (int i = 0; i < 64; i++) c[g_routes[start + i]]++;
    #pragma unroll
    for (int e = 0; e < NEXP; e++) cnt[tid][e] = c[e];
    __syncthreads();
    if (tid == 0) {
        int tot[NEXP];
        for (int e = 0; e < NEXP; e++) {
            int run = 0;
            for (int t = 0; t < 256; t++) { int v = cnt[t][e]; cnt[t][e] = run; run += v; }
            tot[e] = run;
        }
        int accb = 0;
        for (int e = 0; e < NEXP; e++) {
            sbase[e] = accb; g_base[e] = accb; g_count[e] = tot[e]; accb += tot[e];
        }
    }
    __syncthreads();
    int off[NEXP];
    #pragma unroll
    for (int e = 0; e < NEXP; e++) off[e] = sbase[e] + cnt[tid][e];
    for (int i = 0; i < 64; i++) {
        int t = start + i;
        int e = g_routes[t];
        g_perm[off[e]++] = t;                            // stable: chunk-order within thread
    }
}

// ---------------- kernel 4/5: grouped GEMM (fp16 HMMA, fp32 accum) -----------
// FIRST=true : H = relu(Xs[perm] @ W1[e] + b1[e])  -> g_H (fp16, sorted rows)
// FIRST=false: out = H @ W2[e] + b2[e]             -> outF (fp32, sorted rows)
template<int K, int N, bool FIRST>
__global__ __launch_bounds__(256) void ffn_gemm(const float* __restrict__ biasAll,
                                                float* __restrict__ outF) {
    constexpr int BM = 128, BN = 128, BK = 32;
    int e = blockIdx.z;
    int cntE = g_count[e];
    int mt = blockIdx.y * BM;
    if (mt >= cntE) return;                              // empty tile -> cheap exit
    int m0 = g_base[e] + mt;
    int rows = cntE - mt; if (rows > BM) rows = BM;
    int n0 = blockIdx.x * BN;

    const __half* A  = FIRST ? g_xs : g_H;
    const __half* Bp = (FIRST ? g_W1h : g_W2h) + (size_t)e * K * N + n0;
    const float* bias = biasAll + (size_t)e * N;

    __shared__ __half As[BM][BK + 8];                    // 80B row stride (16B-mult)
    __shared__ __half Bs[BK][BN + 8];                    // 272B row stride
    __shared__ int sperm[BM];

    int tid = threadIdx.x, lane = tid & 31, warp = tid >> 5;
    int wm = warp & 1, wn = warp >> 1;                   // 2x4 warp grid, warp tile 64x32

    if constexpr (FIRST) {
        if (tid < BM) sperm[tid] = (tid < rows) ? g_perm[m0 + tid] : 0;
        __syncthreads();
    }

    float acc[4][4][4];
    #pragma unroll
    for (int a = 0; a < 4; a++)
        #pragma unroll
        for (int b = 0; b < 4; b++)
            #pragma unroll
            for (int cdx = 0; cdx < 4; cdx++) acc[a][b][cdx] = 0.f;

    #pragma unroll 1
    for (int k0 = 0; k0 < K; k0 += BK) {
        // A tile: 128x32 halves = 512 uint4, 2 per thread
        #pragma unroll
        for (int p = 0; p < 2; p++) {
            int v = tid + p * 256;
            int r = v >> 2, kc = (v & 3) << 3;
            uint4 val = make_uint4(0u, 0u, 0u, 0u);
            if (r < rows) {
                size_t arow = FIRST ? (size_t)sperm[r] : (size_t)(m0 + r);
                val = *reinterpret_cast<const uint4*>(A + arow * K + k0 + kc);
            }
            *reinterpret_cast<uint4*>(&As[r][kc]) = val;
        }
        // B tile: 32x128 halves = 512 uint4
        #pragma unroll
        for (int p = 0; p < 2; p++) {
            int v = tid + p * 256;
            int r = v >> 4, ncol = (v & 15) << 3;
            *reinterpret_cast<uint4*>(&Bs[r][ncol]) =
                *reinterpret_cast<const uint4*>(Bp + (size_t)(k0 + r) * N + ncol);
        }
        __syncthreads();

        #pragma unroll
        for (int ks = 0; ks < 2; ks++) {
            int kk = ks * 16;
            uint32_t af[4][4];
            #pragma unroll
            for (int mi = 0; mi < 4; mi++) {
                uint32_t ad = smem_u32(&As[wm * 64 + mi * 16 + (lane & 15)][kk + ((lane >> 4) << 3)]);
                ldm_x4(af[mi], ad);
            }
            #pragma unroll
            for (int nh = 0; nh < 2; nh++) {
                uint32_t bf[4];
                uint32_t bd = smem_u32(&Bs[kk + (lane & 15)][wn * 32 + nh * 16 + ((lane >> 4) << 3)]);
                ldm_x4_t(bf, bd);
                #pragma unroll
                for (int mi = 0; mi < 4; mi++) {
                    mma_16816(acc[mi][nh * 2 + 0], af[mi], bf[0], bf[1]);
                    mma_16816(acc[mi][nh * 2 + 1], af[mi], bf[2], bf[3]);
                }
            }
        }
        __syncthreads();
    }

    // epilogue: +bias, (relu->fp16) or fp32 store; rows are output-order contiguous
    #pragma unroll
    for (int mi = 0; mi < 4; mi++) {
        #pragma unroll
        for (int ni = 0; ni < 4; ni++) {
            int col = wn * 32 + ni * 8 + (lane & 3) * 2;
            int gn = n0 + col;
            float bv0 = __ldg(&bias[gn]);
            float bv1 = __ldg(&bias[gn + 1]);
            #pragma unroll
            for (int h = 0; h < 2; h++) {
                int row = wm * 64 + mi * 16 + (lane >> 2) + h * 8;
                if (row < rows) {
                    float v0 = acc[mi][ni][2 * h + 0] + bv0;
                    float v1 = acc[mi][ni][2 * h + 1] + bv1;
                    size_t goff = (size_t)(m0 + row) * N + gn;
                    if constexpr (FIRST) {
                        v0 = fmaxf(v0, 0.f); v1 = fmaxf(v1, 0.f);
                        *reinterpret_cast<__half2*>(g_H + goff) = __floats2half2_rn(v0, v1);
                    } else {
                        *reinterpret_cast<float2*>(outF + goff) = make_float2(v0, v1);
                    }
                }
            }
        }
    }
}

// ---------------- launcher ----------------------------------------------------
extern "C" void kernel_launch(void* const* d_in, const int* in_sizes, int n_in,
                              void* d_out, int out_size) {
    const float* x  = (const float*)d_in[0];   // [8,2048,512]
    const float* Wg = (const float*)d_in[1];   // [512,8]
    const float* bg = (const float*)d_in[2];   // [8]
    const float* W1 = (const float*)d_in[3];   // [8,512,2048]
    const float* b1 = (const float*)d_in[4];   // [8,2048]
    const float* W2 = (const float*)d_in[5];   // [8,2048,512]
    const float* b2 = (const float*)d_in[6];   // [8,512]
    float* out = (float*)d_out;                // [8,2048,512]

    convw_kernel<<<16384, 256>>>(W1, W2);
    route_kernel<<<T_TOK / 8, 256>>>(x, Wg, bg);
    scan_kernel<<<1, 256>>>();
    {
        dim3 g(FFDIM / 128, T_TOK / 128, NEXP);
        ffn_gemm<DMODEL, FFDIM, true><<<g, 256>>>(b1, nullptr);
    }
    {
        dim3 g(DMODEL / 128, T_TOK / 128, NEXP);
        ffn_gemm<FFDIM, DMODEL, false><<<g, 256>>>(b2, out);
    }
}

// round 16
// speedup vs baseline: 1.0062x; 1.0030x over previous
#include <cuda_runtime.h>
#include <cuda_fp16.h>
#include <cstdint>

// Problem constants (fixed shapes)
#define T_TOK  16384
#define DMODEL 512
#define FFDIM  2048
#define NEXP   8

// ---------------- device scratch (alloc-free rule: __device__ globals) --------
__device__ __align__(128) __half g_xs [(size_t)T_TOK * DMODEL];          // scaled tokens fp16
__device__ __align__(128) __half g_H  [(size_t)T_TOK * FFDIM];           // hidden acts fp16 (sorted order)
__device__ __align__(128) __half g_W1h[(size_t)NEXP * DMODEL * FFDIM];   // fp16 weights
__device__ __align__(128) __half g_W2h[(size_t)NEXP * FFDIM * DMODEL];
__device__ int g_routes[T_TOK];
__device__ int g_perm  [T_TOK];
__device__ int g_base  [NEXP];
__device__ int g_count [NEXP];

// ---------------- small PTX helpers ------------------------------------------
__device__ __forceinline__ uint32_t smem_u32(const void* p) {
    return (uint32_t)__cvta_generic_to_shared(p);
}
__device__ __forceinline__ void ldm_x4(uint32_t r[4], uint32_t addr) {
    asm volatile("ldmatrix.sync.aligned.m8n8.x4.shared.b16 {%0,%1,%2,%3}, [%4];\n"
                 : "=r"(r[0]), "=r"(r[1]), "=r"(r[2]), "=r"(r[3]) : "r"(addr));
}
__device__ __forceinline__ void ldm_x4_t(uint32_t r[4], uint32_t addr) {
    asm volatile("ldmatrix.sync.aligned.m8n8.x4.trans.shared.b16 {%0,%1,%2,%3}, [%4];\n"
                 : "=r"(r[0]), "=r"(r[1]), "=r"(r[2]), "=r"(r[3]) : "r"(addr));
}
__device__ __forceinline__ void mma_16816(float c[4], const uint32_t a[4],
                                          uint32_t b0, uint32_t b1) {
    asm volatile("mma.sync.aligned.m16n8k16.row.col.f32.f16.f16.f32 "
                 "{%0,%1,%2,%3}, {%4,%5,%6,%7}, {%8,%9}, {%0,%1,%2,%3};\n"
                 : "+f"(c[0]), "+f"(c[1]), "+f"(c[2]), "+f"(c[3])
                 : "r"(a[0]), "r"(a[1]), "r"(a[2]), "r"(a[3]), "r"(b0), "r"(b1));
}

// ---------------- kernel 1: weight fp32 -> fp16 ------------------------------
__global__ __launch_bounds__(256) void convw_kernel(const float* __restrict__ W1,
                                                    const float* __restrict__ W2) {
    size_t i = (size_t)blockIdx.x * 256 + threadIdx.x;   // over 4,194,304 float2 pairs
    float2 a = *reinterpret_cast<const float2*>(W1 + 2 * i);
    *reinterpret_cast<__half2*>(g_W1h + 2 * i) = __floats2half2_rn(a.x, a.y);
    float2 b = *reinterpret_cast<const float2*>(W2 + 2 * i);
    *reinterpret_cast<__half2*>(g_W2h + 2 * i) = __floats2half2_rn(b.x, b.y);
}

// ---------------- kernel 2: routing (warp per token) --------------------------
__global__ __launch_bounds__(256) void route_kernel(const float* __restrict__ x,
                                                    const float* __restrict__ Wg,
                                                    const float* __restrict__ bg) {
    __shared__ float sWg[DMODEL * NEXP];                 // 16KB
    for (int i = threadIdx.x; i < DMODEL * NEXP; i += 256) sWg[i] = Wg[i];
    __syncthreads();

    int warp = threadIdx.x >> 5, lane = threadIdx.x & 31;
    int t = blockIdx.x * 8 + warp;
    const float* xp = x + (size_t)t * DMODEL;

    float4 fv[4];
    float acc[NEXP];
    #pragma unroll
    for (int e = 0; e < NEXP; e++) acc[e] = 0.f;

    #pragma unroll
    for (int i = 0; i < 4; i++) {
        int d0 = (lane + 32 * i) * 4;
        fv[i] = *reinterpret_cast<const float4*>(xp + d0);
        const float* w = &sWg[d0 * NEXP];
        #pragma unroll
        for (int e = 0; e < NEXP; e++)
            acc[e] += fv[i].x * w[e] + fv[i].y * w[NEXP + e]
                    + fv[i].z * w[2 * NEXP + e] + fv[i].w * w[3 * NEXP + e];
    }
    #pragma unroll
    for (int off = 16; off; off >>= 1)
        #pragma unroll
        for (int e = 0; e < NEXP; e++) acc[e] += __shfl_xor_sync(0xffffffffu, acc[e], off);

    #pragma unroll
    for (int e = 0; e < NEXP; e++) acc[e] += __ldg(&bg[e]);

    float lmax = acc[0]; int arg = 0;
    #pragma unroll
    for (int e = 1; e < NEXP; e++) if (acc[e] > lmax) { lmax = acc[e]; arg = e; }  // first-max tie-break
    float sum = 0.f;
    #pragma unroll
    for (int e = 0; e < NEXP; e++) sum += __expf(acc[e] - lmax);
    float pmax = 1.f / sum;                              // softmax max prob

    if (lane == 0) g_routes[t] = arg;

    __half* outp = g_xs + (size_t)t * DMODEL;
    #pragma unroll
    for (int i = 0; i < 4; i++) {
        int d0 = (lane + 32 * i) * 4;
        *reinterpret_cast<__half2*>(outp + d0)     = __floats2half2_rn(fv[i].x * pmax, fv[i].y * pmax);
        *reinterpret_cast<__half2*>(outp + d0 + 2) = __floats2half2_rn(fv[i].z * pmax, fv[i].w * pmax);
    }
}

// ---------------- kernel 3: stable counting sort (1 CTA) ----------------------
__global__ __launch_bounds__(256) void scan_kernel() {
    __shared__ int cnt[256][NEXP];                       // 8KB
    __shared__ int sbase[NEXP];
    int tid = threadIdx.x;
    int c[NEXP];
    #pragma unroll
    for (int e = 0; e < NEXP; e++) c[e] = 0;
    int start = tid * 64;                                // 256*64 = 16384
    #pragma unroll 8
    for (int i = 0; i < 64; i++) c[g_routes[start + i]]++;
    #pragma unroll
    for (int e = 0; e < NEXP; e++) cnt[tid][e] = c[e];
    __syncthreads();
    if (tid == 0) {
        int tot[NEXP];
        for (int e = 0; e < NEXP; e++) {
            int run = 0;
            for (int t = 0; t < 256; t++) { int v = cnt[t][e]; cnt[t][e] = run; run += v; }
            tot[e] = run;
        }
        int accb = 0;
        for (int e = 0; e < NEXP; e++) {
            sbase[e] = accb; g_base[e] = accb; g_count[e] = tot[e]; accb += tot[e];
        }
    }
    __syncthreads();
    int off[NEXP];
    #pragma unroll
    for (int e = 0; e < NEXP; e++) off[e] = sbase[e] + cnt[tid][e];
    for (int i = 0; i < 64; i++) {
        int t = start + i;
        int e = g_routes[t];
        g_perm[off[e]++] = t;                            // stable: chunk-order within thread
    }
}

// ---------------- kernel 4/5: grouped GEMM (fp16 HMMA, fp32 accum) -----------
// FIRST=true : H = relu(Xs[perm] @ W1[e] + b1[e])  -> g_H (fp16, sorted rows)
// FIRST=false: out = H @ W2[e] + b2[e]             -> outF (fp32, sorted rows)
template<int K, int N, bool FIRST>
__global__ __launch_bounds__(256) void ffn_gemm(const float* __restrict__ biasAll,
                                                float* __restrict__ outF) {
    constexpr int BM = 128, BN = 128, BK = 32;
    int e = blockIdx.z;
    int cntE = g_count[e];
    int mt = blockIdx.y * BM;
    if (mt >= cntE) return;                              // empty tile -> cheap exit
    int m0 = g_base[e] + mt;
    int rows = cntE - mt; if (rows > BM) rows = BM;
    int n0 = blockIdx.x * BN;

    const __half* A  = FIRST ? g_xs : g_H;
    const __half* Bp = (FIRST ? g_W1h : g_W2h) + (size_t)e * K * N + n0;
    const float* bias = biasAll + (size_t)e * N;

    __shared__ __half As[BM][BK + 8];                    // 80B row stride (16B-mult)
    __shared__ __half Bs[BK][BN + 8];                    // 272B row stride
    __shared__ int sperm[BM];

    int tid = threadIdx.x, lane = tid & 31, warp = tid >> 5;
    int wm = warp & 1, wn = warp >> 1;                   // 2x4 warp grid, warp tile 64x32

    if constexpr (FIRST) {
        if (tid < BM) sperm[tid] = (tid < rows) ? g_perm[m0 + tid] : 0;
        __syncthreads();
    }

    float acc[4][4][4];
    #pragma unroll
    for (int a = 0; a < 4; a++)
        #pragma unroll
        for (int b = 0; b < 4; b++)
            #pragma unroll
            for (int cdx = 0; cdx < 4; cdx++) acc[a][b][cdx] = 0.f;

    #pragma unroll 1
    for (int k0 = 0; k0 < K; k0 += BK) {
        // A tile: 128x32 halves = 512 uint4, 2 per thread
        #pragma unroll
        for (int p = 0; p < 2; p++) {
            int v = tid + p * 256;
            int r = v >> 2, kc = (v & 3) << 3;
            uint4 val = make_uint4(0u, 0u, 0u, 0u);
            if (r < rows) {
                size_t arow = FIRST ? (size_t)sperm[r] : (size_t)(m0 + r);
                val = *reinterpret_cast<const uint4*>(A + arow * K + k0 + kc);
            }
            *reinterpret_cast<uint4*>(&As[r][kc]) = val;
        }
        // B tile: 32x128 halves = 512 uint4
        #pragma unroll
        for (int p = 0; p < 2; p++) {
            int v = tid + p * 256;
            int r = v >> 4, ncol = (v & 15) << 3;
            *reinterpret_cast<uint4*>(&Bs[r][ncol]) =
                *reinterpret_cast<const uint4*>(Bp + (size_t)(k0 + r) * N + ncol);
        }
        __syncthreads();

        #pragma unroll
        for (int ks = 0; ks < 2; ks++) {
            int kk = ks * 16;
            uint32_t af[4][4];
            #pragma unroll
            for (int mi = 0; mi < 4; mi++) {
                uint32_t ad = smem_u32(&As[wm * 64 + mi * 16 + (lane & 15)][kk + ((lane >> 4) << 3)]);
                ldm_x4(af[mi], ad);
            }
            #pragma unroll
            for (int nh = 0; nh < 2; nh++) {
                uint32_t bf[4];
                uint32_t bd = smem_u32(&Bs[kk + (lane & 15)][wn * 32 + nh * 16 + ((lane >> 4) << 3)]);
                ldm_x4_t(bf, bd);
                #pragma unroll
                for (int mi = 0; mi < 4; mi++) {
                    mma_16816(acc[mi][nh * 2 + 0], af[mi], bf[0], bf[1]);
                    mma_16816(acc[mi][nh * 2 + 1], af[mi], bf[2], bf[3]);
                }
            }
        }
        __syncthreads();
    }

    // epilogue: +bias, (relu->fp16) or fp32 store; rows are output-order contiguous
    #pragma unroll
    for (int mi = 0; mi < 4; mi++) {
        #pragma unroll
        for (int ni = 0; ni < 4; ni++) {
            int col = wn * 32 + ni * 8 + (lane & 3) * 2;
            int gn = n0 + col;
            float bv0 = __ldg(&bias[gn]);
            float bv1 = __ldg(&bias[gn + 1]);
            #pragma unroll
            for (int h = 0; h < 2; h++) {
                int row = wm * 64 + mi * 16 + (lane >> 2) + h * 8;
                if (row < rows) {
                    float v0 = acc[mi][ni][2 * h + 0] + bv0;
                    float v1 = acc[mi][ni][2 * h + 1] + bv1;
                    size_t goff = (size_t)(m0 + row) * N + gn;
                    if constexpr (FIRST) {
                        v0 = fmaxf(v0, 0.f); v1 = fmaxf(v1, 0.f);
                        *reinterpret_cast<__half2*>(g_H + goff) = __floats2half2_rn(v0, v1);
                    } else {
                        *reinterpret_cast<float2*>(outF + goff) = make_float2(v0, v1);
                    }
                }
            }
        }
    }
}

// ---------------- launcher ----------------------------------------------------
extern "C" void kernel_launch(void* const* d_in, const int* in_sizes, int n_in,
                              void* d_out, int out_size) {
    const float* x  = (const float*)d_in[0];   // [8,2048,512]
    const float* Wg = (const float*)d_in[1];   // [512,8]
    const float* bg = (const float*)d_in[2];   // [8]
    const float* W1 = (const float*)d_in[3];   // [8,512,2048]
    const float* b1 = (const float*)d_in[4];   // [8,2048]
    const float* W2 = (const float*)d_in[5];   // [8,2048,512]
    const float* b2 = (const float*)d_in[6];   // [8,512]
    float* out = (float*)d_out;                // [8,2048,512]

    convw_kernel<<<16384, 256>>>(W1, W2);
    route_kernel<<<T_TOK / 8, 256>>>(x, Wg, bg);
    scan_kernel<<<1, 256>>>();
    {
        dim3 g(FFDIM / 128, T_TOK / 128, NEXP);
        ffn_gemm<DMODEL, FFDIM, true><<<g, 256>>>(b1, nullptr);
    }
    {
        dim3 g(DMODEL / 128, T_TOK / 128, NEXP);
        ffn_gemm<FFDIM, DMODEL, false><<<g, 256>>>(b2, out);
    }
}